// round 2
// baseline (speedup 1.0000x reference)
#include <cuda_runtime.h>
#include <cuda_bf16.h>
#include <mma.h>
#include <cstdint>

using namespace nvcuda;

#define DIM   1024
#define SEQ   1024
#define BATCH 4
#define NH    16
#define HD    64
#define ROWS  (BATCH * SEQ)   // 4096

// ---- scratch (static device globals; no runtime allocation) ----
__device__ float g_q[ROWS * DIM];
__device__ float g_k[ROWS * DIM];
__device__ float g_v[ROWS * DIM];
__device__ float g_ao[ROWS * DIM];

__device__ __forceinline__ float tf32r(float x) {
    uint32_t u;
    asm("cvt.rna.tf32.f32 %0, %1;" : "=r"(u) : "f"(x));
    return __uint_as_float(u);
}

__device__ __forceinline__ void mma_tf32(float c[4], const uint32_t a[4],
                                         uint32_t b0, uint32_t b1) {
    asm volatile(
        "mma.sync.aligned.m16n8k8.row.col.f32.tf32.tf32.f32 "
        "{%0,%1,%2,%3}, {%4,%5,%6,%7}, {%8,%9}, {%0,%1,%2,%3};"
        : "+f"(c[0]), "+f"(c[1]), "+f"(c[2]), "+f"(c[3])
        : "r"(a[0]), "r"(a[1]), "r"(a[2]), "r"(a[3]), "r"(b0), "r"(b1));
}

// ============================================================================
// C[m,n] = sum_k A[m,k] * B[n,k]   (A: MxK row-major, B: NxK row-major)
// 128x128 tile per block, BK=32, 8 warps (2x4), each warp 64x32 via wmma tf32.
// ============================================================================
__global__ __launch_bounds__(256) void gemm_tn(const float* __restrict__ A,
                                               const float* __restrict__ B,
                                               float* __restrict__ C,
                                               int M, int N, int K) {
    __shared__ float As[128][36];
    __shared__ float Bs[128][36];

    const int tid  = threadIdx.x;
    const int warp = tid >> 5;
    const int wm   = warp >> 2;   // 0..1  -> 64 rows each
    const int wn   = warp & 3;    // 0..3  -> 32 cols each
    const int bm   = blockIdx.y * 128;
    const int bn   = blockIdx.x * 128;

    wmma::fragment<wmma::accumulator, 16, 16, 8, float> acc[4][2];
#pragma unroll
    for (int i = 0; i < 4; i++)
#pragma unroll
        for (int j = 0; j < 2; j++) wmma::fill_fragment(acc[i][j], 0.0f);

    for (int k0 = 0; k0 < K; k0 += 32) {
#pragma unroll
        for (int it = 0; it < 4; it++) {
            int idx = tid + it * 256;          // 0..1023
            int r   = idx >> 3;                // 128 rows
            int c4  = idx & 7;                 // 8 float4 per row
            float4 va = *(const float4*)(A + (size_t)(bm + r) * K + k0 + c4 * 4);
            As[r][c4 * 4 + 0] = tf32r(va.x);
            As[r][c4 * 4 + 1] = tf32r(va.y);
            As[r][c4 * 4 + 2] = tf32r(va.z);
            As[r][c4 * 4 + 3] = tf32r(va.w);
            float4 vb = *(const float4*)(B + (size_t)(bn + r) * K + k0 + c4 * 4);
            Bs[r][c4 * 4 + 0] = tf32r(vb.x);
            Bs[r][c4 * 4 + 1] = tf32r(vb.y);
            Bs[r][c4 * 4 + 2] = tf32r(vb.z);
            Bs[r][c4 * 4 + 3] = tf32r(vb.w);
        }
        __syncthreads();

#pragma unroll
        for (int kk = 0; kk < 4; kk++) {
            wmma::fragment<wmma::matrix_a, 16, 16, 8, wmma::precision::tf32,
                           wmma::row_major> af[4];
            wmma::fragment<wmma::matrix_b, 16, 16, 8, wmma::precision::tf32,
                           wmma::col_major> bf[2];
#pragma unroll
            for (int i = 0; i < 4; i++)
                wmma::load_matrix_sync(af[i], &As[wm * 64 + i * 16][kk * 8], 36);
#pragma unroll
            for (int j = 0; j < 2; j++)
                wmma::load_matrix_sync(bf[j], &Bs[wn * 32 + j * 16][kk * 8], 36);
#pragma unroll
            for (int i = 0; i < 4; i++)
#pragma unroll
                for (int j = 0; j < 2; j++)
                    wmma::mma_sync(acc[i][j], af[i], bf[j], acc[i][j]);
        }
        __syncthreads();
    }

#pragma unroll
    for (int i = 0; i < 4; i++)
#pragma unroll
        for (int j = 0; j < 2; j++)
            wmma::store_matrix_sync(
                C + (size_t)(bm + wm * 64 + i * 16) * N + bn + wn * 32 + j * 16,
                acc[i][j], N, wmma::mem_row_major);
}

// ============================================================================
// RoPE over the FULL last dim (1024): pair (2j, 2j+1), pos = row % SEQ.
// ============================================================================
__global__ __launch_bounds__(256) void rope_kernel(float* __restrict__ X) {
    int idx = blockIdx.x * blockDim.x + threadIdx.x;   // over ROWS * DIM/2 pairs
    if (idx >= ROWS * (DIM / 2)) return;
    int j   = idx & (DIM / 2 - 1);
    int row = idx >> 9;
    int pos = row & (SEQ - 1);
    // freq = 10000^(-2j/1024) = exp(-2j * ln(10000)/1024)
    float freq = expf((float)(-2 * j) * (9.210340371976184f / (float)DIM));
    float ang  = (float)pos * freq;
    float s, c;
    sincosf(ang, &s, &c);
    float2 v = *(float2*)(X + (size_t)idx * 2);
    float x0 = v.x, x1 = v.y;
    v.x = x0 * c - x1 * s;
    v.y = x0 * s + x1 * c;
    *(float2*)(X + (size_t)idx * 2) = v;
}

// ============================================================================
// Flash attention (no mask), per block: one (b,h), 128 query rows.
// 8 warps x 16 rows. K/V tiles of 64 keys staged in smem (tf32), scores via
// mma.sync m16n8k8 tf32 with explicit fragment layout; online softmax with
// quad shuffles; P staged through smem to re-form A fragments for P@V.
// ============================================================================
__global__ __launch_bounds__(256) void attn_kernel(const float* __restrict__ Q,
                                                   const float* __restrict__ K,
                                                   const float* __restrict__ V,
                                                   float* __restrict__ O) {
    extern __shared__ float sm[];
    float(*Ks)[68] = reinterpret_cast<float(*)[68]>(sm);                    // 64x68
    float(*Vs)[72] = reinterpret_cast<float(*)[72]>(sm + 64 * 68);          // 64x72
    float(*Ps)[68] = reinterpret_cast<float(*)[68]>(sm + 64 * 68 + 64 * 72);// 128x68

    const int tid = threadIdx.x, warp = tid >> 5, lane = tid & 31;
    const int gid = lane >> 2, tig = lane & 3;
    const int b = blockIdx.y >> 4, h = blockIdx.y & 15;
    const int qt = blockIdx.x;

    const float* Qb = Q + (size_t)(b * SEQ + qt * 128) * DIM + h * HD;
    const float* Kb = K + (size_t)(b * SEQ) * DIM + h * HD;
    const float* Vb = V + (size_t)(b * SEQ) * DIM + h * HD;

    // Q fragments for this warp's 16 rows (kept in registers, tf32)
    uint32_t qa[8][4];
#pragma unroll
    for (int kk = 0; kk < 8; kk++) {
        int r0 = warp * 16 + gid;
        qa[kk][0] = __float_as_uint(tf32r(Qb[(size_t)r0 * DIM + kk * 8 + tig]));
        qa[kk][1] = __float_as_uint(tf32r(Qb[(size_t)(r0 + 8) * DIM + kk * 8 + tig]));
        qa[kk][2] = __float_as_uint(tf32r(Qb[(size_t)r0 * DIM + kk * 8 + tig + 4]));
        qa[kk][3] = __float_as_uint(tf32r(Qb[(size_t)(r0 + 8) * DIM + kk * 8 + tig + 4]));
    }

    float o[8][4];
#pragma unroll
    for (int j = 0; j < 8; j++) { o[j][0] = 0.f; o[j][1] = 0.f; o[j][2] = 0.f; o[j][3] = 0.f; }
    float m0 = -1e30f, m1 = -1e30f, l0 = 0.f, l1 = 0.f;

    for (int kt = 0; kt < SEQ / 64; kt++) {
        __syncthreads();
#pragma unroll
        for (int it = 0; it < 4; it++) {
            int idx = tid + it * 256;          // 0..1023
            int r = idx >> 4, c4 = idx & 15;   // 64 rows x 16 float4
            float4 kv = *(const float4*)(Kb + (size_t)(kt * 64 + r) * DIM + c4 * 4);
            Ks[r][c4 * 4 + 0] = tf32r(kv.x);
            Ks[r][c4 * 4 + 1] = tf32r(kv.y);
            Ks[r][c4 * 4 + 2] = tf32r(kv.z);
            Ks[r][c4 * 4 + 3] = tf32r(kv.w);
            float4 vv = *(const float4*)(Vb + (size_t)(kt * 64 + r) * DIM + c4 * 4);
            Vs[r][c4 * 4 + 0] = tf32r(vv.x);
            Vs[r][c4 * 4 + 1] = tf32r(vv.y);
            Vs[r][c4 * 4 + 2] = tf32r(vv.z);
            Vs[r][c4 * 4 + 3] = tf32r(vv.w);
        }
        __syncthreads();

        // S = Q * K^T   (16 rows x 64 keys per warp)
        float sc[8][4];
#pragma unroll
        for (int j = 0; j < 8; j++) { sc[j][0] = 0.f; sc[j][1] = 0.f; sc[j][2] = 0.f; sc[j][3] = 0.f; }
#pragma unroll
        for (int kk = 0; kk < 8; kk++) {
#pragma unroll
            for (int j = 0; j < 8; j++) {
                uint32_t b0 = __float_as_uint(Ks[j * 8 + gid][kk * 8 + tig]);
                uint32_t b1 = __float_as_uint(Ks[j * 8 + gid][kk * 8 + tig + 4]);
                mma_tf32(sc[j], qa[kk], b0, b1);
            }
        }

        // online softmax (rows r0 = gid, r1 = gid+8 of this warp's 16)
        float mt0 = -1e30f, mt1 = -1e30f;
#pragma unroll
        for (int j = 0; j < 8; j++) {
            sc[j][0] *= 0.125f; sc[j][1] *= 0.125f;
            sc[j][2] *= 0.125f; sc[j][3] *= 0.125f;
            mt0 = fmaxf(mt0, fmaxf(sc[j][0], sc[j][1]));
            mt1 = fmaxf(mt1, fmaxf(sc[j][2], sc[j][3]));
        }
        mt0 = fmaxf(mt0, __shfl_xor_sync(0xffffffffu, mt0, 1));
        mt0 = fmaxf(mt0, __shfl_xor_sync(0xffffffffu, mt0, 2));
        mt1 = fmaxf(mt1, __shfl_xor_sync(0xffffffffu, mt1, 1));
        mt1 = fmaxf(mt1, __shfl_xor_sync(0xffffffffu, mt1, 2));
        float nm0 = fmaxf(m0, mt0), nm1 = fmaxf(m1, mt1);
        float a0 = __expf(m0 - nm0), a1 = __expf(m1 - nm1);
        float rs0 = 0.f, rs1 = 0.f;
#pragma unroll
        for (int j = 0; j < 8; j++) {
            float p0 = __expf(sc[j][0] - nm0);
            float p1 = __expf(sc[j][1] - nm0);
            float p2 = __expf(sc[j][2] - nm1);
            float p3 = __expf(sc[j][3] - nm1);
            rs0 += p0 + p1; rs1 += p2 + p3;
            Ps[warp * 16 + gid][j * 8 + tig * 2]         = tf32r(p0);
            Ps[warp * 16 + gid][j * 8 + tig * 2 + 1]     = tf32r(p1);
            Ps[warp * 16 + gid + 8][j * 8 + tig * 2]     = tf32r(p2);
            Ps[warp * 16 + gid + 8][j * 8 + tig * 2 + 1] = tf32r(p3);
        }
        rs0 += __shfl_xor_sync(0xffffffffu, rs0, 1);
        rs0 += __shfl_xor_sync(0xffffffffu, rs0, 2);
        rs1 += __shfl_xor_sync(0xffffffffu, rs1, 1);
        rs1 += __shfl_xor_sync(0xffffffffu, rs1, 2);
        l0 = l0 * a0 + rs0; l1 = l1 * a1 + rs1;
        m0 = nm0; m1 = nm1;
#pragma unroll
        for (int j = 0; j < 8; j++) { o[j][0] *= a0; o[j][1] *= a0; o[j][2] *= a1; o[j][3] *= a1; }
        __syncwarp();

        // O += P * V
#pragma unroll
        for (int kk = 0; kk < 8; kk++) {
            uint32_t pa[4];
            pa[0] = __float_as_uint(Ps[warp * 16 + gid][kk * 8 + tig]);
            pa[1] = __float_as_uint(Ps[warp * 16 + gid + 8][kk * 8 + tig]);
            pa[2] = __float_as_uint(Ps[warp * 16 + gid][kk * 8 + tig + 4]);
            pa[3] = __float_as_uint(Ps[warp * 16 + gid + 8][kk * 8 + tig + 4]);
#pragma unroll
            for (int j = 0; j < 8; j++) {
                uint32_t b0 = __float_as_uint(Vs[kk * 8 + tig][j * 8 + gid]);
                uint32_t b1 = __float_as_uint(Vs[kk * 8 + tig + 4][j * 8 + gid]);
                mma_tf32(o[j], pa, b0, b1);
            }
        }
    }

    float il0 = 1.f / l0, il1 = 1.f / l1;
    float* Ob = O + (size_t)(b * SEQ + qt * 128) * DIM + h * HD;
#pragma unroll
    for (int j = 0; j < 8; j++) {
        float2 v0 = make_float2(o[j][0] * il0, o[j][1] * il0);
        float2 v1 = make_float2(o[j][2] * il1, o[j][3] * il1);
        *(float2*)(Ob + (size_t)(warp * 16 + gid) * DIM + j * 8 + tig * 2)     = v0;
        *(float2*)(Ob + (size_t)(warp * 16 + gid + 8) * DIM + j * 8 + tig * 2) = v1;
    }
}

__global__ __launch_bounds__(256) void bias_kernel(float* __restrict__ O,
                                                   const float* __restrict__ bo) {
    int idx = blockIdx.x * blockDim.x + threadIdx.x;   // float4 index
    if (idx >= ROWS * DIM / 4) return;
    float4 v = ((float4*)O)[idx];
    float4 b = ((const float4*)bo)[idx & (DIM / 4 - 1)];
    v.x += b.x; v.y += b.y; v.z += b.z; v.w += b.w;
    ((float4*)O)[idx] = v;
}

// ============================================================================
extern "C" void kernel_launch(void* const* d_in, const int* in_sizes, int n_in,
                              void* d_out, int out_size) {
    const float* x  = (const float*)d_in[0];
    const float* Wq = (const float*)d_in[1];
    const float* Wk = (const float*)d_in[2];
    const float* Wv = (const float*)d_in[3];
    const float* Wo = (const float*)d_in[4];
    const float* bo = (const float*)d_in[5];
    float* out = (float*)d_out;

    float *q, *k, *v, *ao;
    cudaGetSymbolAddress((void**)&q, g_q);
    cudaGetSymbolAddress((void**)&k, g_k);
    cudaGetSymbolAddress((void**)&v, g_v);
    cudaGetSymbolAddress((void**)&ao, g_ao);

    dim3 gg(DIM / 128, ROWS / 128);
    gemm_tn<<<gg, 256>>>(x, Wq, q, ROWS, DIM, DIM);
    gemm_tn<<<gg, 256>>>(x, Wk, k, ROWS, DIM, DIM);
    gemm_tn<<<gg, 256>>>(x, Wv, v, ROWS, DIM, DIM);

    int npairs = ROWS * (DIM / 2);
    rope_kernel<<<(npairs + 255) / 256, 256>>>(q);
    rope_kernel<<<(npairs + 255) / 256, 256>>>(k);

    int smem = (64 * 68 + 64 * 72 + 128 * 68) * 4;   // 70656 B
    cudaFuncSetAttribute(attn_kernel, cudaFuncAttributeMaxDynamicSharedMemorySize, smem);
    attn_kernel<<<dim3(SEQ / 128, BATCH * NH), 256, smem>>>(q, k, v, ao);

    gemm_tn<<<gg, 256>>>(ao, Wo, out, ROWS, DIM, DIM);
    bias_kernel<<<(ROWS * DIM / 4 + 255) / 256, 256>>>(out, bo);
}

// round 5
// speedup vs baseline: 1.3135x; 1.3135x over previous
#include <cuda_runtime.h>
#include <cuda_bf16.h>
#include <mma.h>
#include <cstdint>

using namespace nvcuda;

#define DIM   1024
#define SEQ   1024
#define BATCH 4
#define NH    16
#define HD    64
#define ROWS  (BATCH * SEQ)   // 4096

// ---- scratch (static device globals; no runtime allocation) ----
__device__ float g_q[ROWS * DIM];
__device__ float g_k[ROWS * DIM];
__device__ float g_v[ROWS * DIM];
__device__ float g_ao[ROWS * DIM];

__device__ __forceinline__ float tf32r(float x) {
    uint32_t u;
    asm("cvt.rna.tf32.f32 %0, %1;" : "=r"(u) : "f"(x));
    return __uint_as_float(u);
}

__device__ __forceinline__ void mma_tf32(float c[4], const uint32_t a[4],
                                         uint32_t b0, uint32_t b1) {
    asm volatile(
        "mma.sync.aligned.m16n8k8.row.col.f32.tf32.tf32.f32 "
        "{%0,%1,%2,%3}, {%4,%5,%6,%7}, {%8,%9}, {%0,%1,%2,%3};"
        : "+f"(c[0]), "+f"(c[1]), "+f"(c[2]), "+f"(c[3])
        : "r"(a[0]), "r"(a[1]), "r"(a[2]), "r"(a[3]), "r"(b0), "r"(b1));
}

__device__ __forceinline__ void cpa16(float* s, const float* g) {
    uint32_t sa = (uint32_t)__cvta_generic_to_shared(s);
    asm volatile("cp.async.cg.shared.global [%0], [%1], 16;" :: "r"(sa), "l"(g));
}

// ============================================================================
// GEMM core: C[m,n] = sum_k A[m,k]*B[n,k], M-tile 128, N-tile 128, BK=32,
// 2-stage cp.async double buffering, wmma tf32, fp32 accumulate.
// If bias != nullptr: stage accumulators through smem and store C with bias.
// Dynamic smem layout (floats): As stage0 [0,4608), As stage1 [4608,9216),
//                               Bs stage0 [9216,13824), Bs stage1 [13824,18432)
// ============================================================================
__device__ __forceinline__ void gemm_core(const float* __restrict__ A,
                                          const float* __restrict__ Bw,
                                          float* __restrict__ C,
                                          const float* __restrict__ bias,
                                          int bm, int bn, float* sm) {
    const int tid  = threadIdx.x;
    const int warp = tid >> 5;
    const int wm   = warp >> 2;   // 0..1
    const int wn   = warp & 3;    // 0..3

    float* As0 = sm;
    float* Bs0 = sm + 9216;

    wmma::fragment<wmma::accumulator, 16, 16, 8, float> acc[4][2];
#pragma unroll
    for (int i = 0; i < 4; i++)
#pragma unroll
        for (int j = 0; j < 2; j++) wmma::fill_fragment(acc[i][j], 0.0f);

    const int r  = tid >> 1;             // 128 rows, 2 threads per row
    const int c4 = (tid & 1) * 4;        // float4 index 0 or 4

    // prefetch stage 0
    {
        float* As = As0;
        float* Bs = Bs0;
#pragma unroll
        for (int it = 0; it < 4; it++) {   // 4 float4 per thread per array
            int rr = r;                    // row
            int cc = c4 + (it & 3);        // hmm -- see expanded below
            (void)rr; (void)cc;
        }
        // expanded: each thread does 4 slots: idx = tid + it*256 over 1024 slots
#pragma unroll
        for (int it = 0; it < 4; it++) {
            int idx = tid + it * 256;
            int rr = idx >> 3, cc = idx & 7;
            cpa16(As + rr * 36 + cc * 4, A + (size_t)(bm + rr) * DIM + cc * 4);
            cpa16(Bs + rr * 36 + cc * 4, Bw + (size_t)(bn + rr) * DIM + cc * 4);
        }
        asm volatile("cp.async.commit_group;");
    }

    const int NIT = DIM / 32;   // 32
    for (int itn = 0; itn < NIT; itn++) {
        if (itn + 1 < NIT) {
            float* As = As0 + ((itn + 1) & 1) * 4608;
            float* Bs = Bs0 + ((itn + 1) & 1) * 4608;
            int k0 = (itn + 1) * 32;
#pragma unroll
            for (int it = 0; it < 4; it++) {
                int idx = tid + it * 256;
                int rr = idx >> 3, cc = idx & 7;
                cpa16(As + rr * 36 + cc * 4, A + (size_t)(bm + rr) * DIM + k0 + cc * 4);
                cpa16(Bs + rr * 36 + cc * 4, Bw + (size_t)(bn + rr) * DIM + k0 + cc * 4);
            }
            asm volatile("cp.async.commit_group;");
            asm volatile("cp.async.wait_group 1;");
        } else {
            asm volatile("cp.async.wait_group 0;");
        }
        __syncthreads();

        float* As = As0 + (itn & 1) * 4608;
        float* Bs = Bs0 + (itn & 1) * 4608;
#pragma unroll
        for (int kk = 0; kk < 4; kk++) {
            wmma::fragment<wmma::matrix_a, 16, 16, 8, wmma::precision::tf32,
                           wmma::row_major> af[4];
            wmma::fragment<wmma::matrix_b, 16, 16, 8, wmma::precision::tf32,
                           wmma::col_major> bf[2];
#pragma unroll
            for (int i = 0; i < 4; i++) {
                wmma::load_matrix_sync(af[i], As + (wm * 64 + i * 16) * 36 + kk * 8, 36);
#pragma unroll
                for (int e = 0; e < af[i].num_elements; e++) af[i].x[e] = tf32r(af[i].x[e]);
            }
#pragma unroll
            for (int j = 0; j < 2; j++) {
                wmma::load_matrix_sync(bf[j], Bs + (wn * 32 + j * 16) * 36 + kk * 8, 36);
#pragma unroll
                for (int e = 0; e < bf[j].num_elements; e++) bf[j].x[e] = tf32r(bf[j].x[e]);
            }
#pragma unroll
            for (int i = 0; i < 4; i++)
#pragma unroll
                for (int j = 0; j < 2; j++)
                    wmma::mma_sync(acc[i][j], af[i], bf[j], acc[i][j]);
        }
        __syncthreads();
    }

    if (bias == nullptr) {
#pragma unroll
        for (int i = 0; i < 4; i++)
#pragma unroll
            for (int j = 0; j < 2; j++)
                wmma::store_matrix_sync(
                    C + (size_t)(bm + wm * 64 + i * 16) * DIM + bn + wn * 32 + j * 16,
                    acc[i][j], DIM, wmma::mem_row_major);
    } else {
        // stage through smem (buffers dead after final sync), add bias, store.
        float* St = sm;   // 128 x 132 floats = 16896 <= 18432 available
#pragma unroll
        for (int i = 0; i < 4; i++)
#pragma unroll
            for (int j = 0; j < 2; j++)
                wmma::store_matrix_sync(
                    St + (wm * 64 + i * 16) * 132 + wn * 32 + j * 16,
                    acc[i][j], 132, wmma::mem_row_major);
        __syncthreads();
#pragma unroll
        for (int it = 0; it < 16; it++) {
            int idx = tid + it * 256;          // 4096 float4 slots
            int rr = idx >> 5, cc = idx & 31;  // 128 rows x 32 float4
            float4 v = *(float4*)(St + rr * 132 + cc * 4);
            float4 b = *(const float4*)(bias + bn + cc * 4);
            v.x += b.x; v.y += b.y; v.z += b.z; v.w += b.w;
            *(float4*)(C + (size_t)(bm + rr) * DIM + bn + cc * 4) = v;
        }
    }
}

__global__ __launch_bounds__(256) void gemm_out(const float* __restrict__ A,
                                                const float* __restrict__ Bw,
                                                float* __restrict__ C,
                                                const float* __restrict__ bias) {
    extern __shared__ float sm[];
    gemm_core(A, Bw, C, bias, blockIdx.y * 128, blockIdx.x * 128, sm);
}

__global__ __launch_bounds__(256) void gemm_qkv(const float* __restrict__ x,
                                                const float* __restrict__ Wq,
                                                const float* __restrict__ Wk,
                                                const float* __restrict__ Wv,
                                                float* __restrict__ q,
                                                float* __restrict__ k,
                                                float* __restrict__ v) {
    extern __shared__ float sm[];
    const int z = blockIdx.z;
    const float* Bw = (z == 0) ? Wq : (z == 1) ? Wk : Wv;
    float* C = (z == 0) ? q : (z == 1) ? k : v;
    gemm_core(x, Bw, C, nullptr, blockIdx.y * 128, blockIdx.x * 128, sm);
}

// ============================================================================
// RoPE over the FULL last dim (1024): pair (2j, 2j+1), pos = row % SEQ.
// ============================================================================
__global__ __launch_bounds__(256) void rope_kernel(float* __restrict__ X) {
    int idx = blockIdx.x * blockDim.x + threadIdx.x;   // over ROWS * DIM/2 pairs
    if (idx >= ROWS * (DIM / 2)) return;
    int j   = idx & (DIM / 2 - 1);
    int row = idx >> 9;
    int pos = row & (SEQ - 1);
    float freq = expf((float)(-2 * j) * (9.210340371976184f / (float)DIM));
    float ang  = (float)pos * freq;
    float s, c;
    sincosf(ang, &s, &c);
    float2 v = *(float2*)(X + (size_t)idx * 2);
    float x0 = v.x, x1 = v.y;
    v.x = x0 * c - x1 * s;
    v.y = x0 * s + x1 * c;
    *(float2*)(X + (size_t)idx * 2) = v;
}

// ============================================================================
// Flash attention (no mask), per block: one (b,h), 128 query rows.
// ============================================================================
__global__ __launch_bounds__(256) void attn_kernel(const float* __restrict__ Q,
                                                   const float* __restrict__ K,
                                                   const float* __restrict__ V,
                                                   float* __restrict__ O) {
    extern __shared__ float sm[];
    float(*Ks)[68] = reinterpret_cast<float(*)[68]>(sm);                    // 64x68
    float(*Vs)[72] = reinterpret_cast<float(*)[72]>(sm + 64 * 68);          // 64x72
    float(*Ps)[68] = reinterpret_cast<float(*)[68]>(sm + 64 * 68 + 64 * 72);// 128x68

    const int tid = threadIdx.x, warp = tid >> 5, lane = tid & 31;
    const int gid = lane >> 2, tig = lane & 3;
    const int b = blockIdx.y >> 4, h = blockIdx.y & 15;
    const int qt = blockIdx.x;

    const float* Qb = Q + (size_t)(b * SEQ + qt * 128) * DIM + h * HD;
    const float* Kb = K + (size_t)(b * SEQ) * DIM + h * HD;
    const float* Vb = V + (size_t)(b * SEQ) * DIM + h * HD;

    uint32_t qa[8][4];
#pragma unroll
    for (int kk = 0; kk < 8; kk++) {
        int r0 = warp * 16 + gid;
        qa[kk][0] = __float_as_uint(tf32r(Qb[(size_t)r0 * DIM + kk * 8 + tig]));
        qa[kk][1] = __float_as_uint(tf32r(Qb[(size_t)(r0 + 8) * DIM + kk * 8 + tig]));
        qa[kk][2] = __float_as_uint(tf32r(Qb[(size_t)r0 * DIM + kk * 8 + tig + 4]));
        qa[kk][3] = __float_as_uint(tf32r(Qb[(size_t)(r0 + 8) * DIM + kk * 8 + tig + 4]));
    }

    float o[8][4];
#pragma unroll
    for (int j = 0; j < 8; j++) { o[j][0] = 0.f; o[j][1] = 0.f; o[j][2] = 0.f; o[j][3] = 0.f; }
    float m0 = -1e30f, m1 = -1e30f, l0 = 0.f, l1 = 0.f;

    for (int kt = 0; kt < SEQ / 64; kt++) {
        __syncthreads();
#pragma unroll
        for (int it = 0; it < 4; it++) {
            int idx = tid + it * 256;
            int r = idx >> 4, c4 = idx & 15;
            float4 kv = *(const float4*)(Kb + (size_t)(kt * 64 + r) * DIM + c4 * 4);
            Ks[r][c4 * 4 + 0] = tf32r(kv.x);
            Ks[r][c4 * 4 + 1] = tf32r(kv.y);
            Ks[r][c4 * 4 + 2] = tf32r(kv.z);
            Ks[r][c4 * 4 + 3] = tf32r(kv.w);
            float4 vv = *(const float4*)(Vb + (size_t)(kt * 64 + r) * DIM + c4 * 4);
            Vs[r][c4 * 4 + 0] = tf32r(vv.x);
            Vs[r][c4 * 4 + 1] = tf32r(vv.y);
            Vs[r][c4 * 4 + 2] = tf32r(vv.z);
            Vs[r][c4 * 4 + 3] = tf32r(vv.w);
        }
        __syncthreads();

        float sc[8][4];
#pragma unroll
        for (int j = 0; j < 8; j++) { sc[j][0] = 0.f; sc[j][1] = 0.f; sc[j][2] = 0.f; sc[j][3] = 0.f; }
#pragma unroll
        for (int kk = 0; kk < 8; kk++) {
#pragma unroll
            for (int j = 0; j < 8; j++) {
                uint32_t b0 = __float_as_uint(Ks[j * 8 + gid][kk * 8 + tig]);
                uint32_t b1 = __float_as_uint(Ks[j * 8 + gid][kk * 8 + tig + 4]);
                mma_tf32(sc[j], qa[kk], b0, b1);
            }
        }

        float mt0 = -1e30f, mt1 = -1e30f;
#pragma unroll
        for (int j = 0; j < 8; j++) {
            sc[j][0] *= 0.125f; sc[j][1] *= 0.125f;
            sc[j][2] *= 0.125f; sc[j][3] *= 0.125f;
            mt0 = fmaxf(mt0, fmaxf(sc[j][0], sc[j][1]));
            mt1 = fmaxf(mt1, fmaxf(sc[j][2], sc[j][3]));
        }
        mt0 = fmaxf(mt0, __shfl_xor_sync(0xffffffffu, mt0, 1));
        mt0 = fmaxf(mt0, __shfl_xor_sync(0xffffffffu, mt0, 2));
        mt1 = fmaxf(mt1, __shfl_xor_sync(0xffffffffu, mt1, 1));
        mt1 = fmaxf(mt1, __shfl_xor_sync(0xffffffffu, mt1, 2));
        float nm0 = fmaxf(m0, mt0), nm1 = fmaxf(m1, mt1);
        float a0 = __expf(m0 - nm0), a1 = __expf(m1 - nm1);
        float rs0 = 0.f, rs1 = 0.f;
#pragma unroll
        for (int j = 0; j < 8; j++) {
            float p0 = __expf(sc[j][0] - nm0);
            float p1 = __expf(sc[j][1] - nm0);
            float p2 = __expf(sc[j][2] - nm1);
            float p3 = __expf(sc[j][3] - nm1);
            rs0 += p0 + p1; rs1 += p2 + p3;
            Ps[warp * 16 + gid][j * 8 + tig * 2]         = tf32r(p0);
            Ps[warp * 16 + gid][j * 8 + tig * 2 + 1]     = tf32r(p1);
            Ps[warp * 16 + gid + 8][j * 8 + tig * 2]     = tf32r(p2);
            Ps[warp * 16 + gid + 8][j * 8 + tig * 2 + 1] = tf32r(p3);
        }
        rs0 += __shfl_xor_sync(0xffffffffu, rs0, 1);
        rs0 += __shfl_xor_sync(0xffffffffu, rs0, 2);
        rs1 += __shfl_xor_sync(0xffffffffu, rs1, 1);
        rs1 += __shfl_xor_sync(0xffffffffu, rs1, 2);
        l0 = l0 * a0 + rs0; l1 = l1 * a1 + rs1;
        m0 = nm0; m1 = nm1;
#pragma unroll
        for (int j = 0; j < 8; j++) { o[j][0] *= a0; o[j][1] *= a0; o[j][2] *= a1; o[j][3] *= a1; }
        __syncwarp();

#pragma unroll
        for (int kk = 0; kk < 8; kk++) {
            uint32_t pa[4];
            pa[0] = __float_as_uint(Ps[warp * 16 + gid][kk * 8 + tig]);
            pa[1] = __float_as_uint(Ps[warp * 16 + gid + 8][kk * 8 + tig]);
            pa[2] = __float_as_uint(Ps[warp * 16 + gid][kk * 8 + tig + 4]);
            pa[3] = __float_as_uint(Ps[warp * 16 + gid + 8][kk * 8 + tig + 4]);
#pragma unroll
            for (int j = 0; j < 8; j++) {
                uint32_t b0 = __float_as_uint(Vs[kk * 8 + tig][j * 8 + gid]);
                uint32_t b1 = __float_as_uint(Vs[kk * 8 + tig + 4][j * 8 + gid]);
                mma_tf32(o[j], pa, b0, b1);
            }
        }
    }

    float il0 = 1.f / l0, il1 = 1.f / l1;
    float* Ob = O + (size_t)(b * SEQ + qt * 128) * DIM + h * HD;
#pragma unroll
    for (int j = 0; j < 8; j++) {
        float2 v0 = make_float2(o[j][0] * il0, o[j][1] * il0);
        float2 v1 = make_float2(o[j][2] * il1, o[j][3] * il1);
        *(float2*)(Ob + (size_t)(warp * 16 + gid) * DIM + j * 8 + tig * 2)     = v0;
        *(float2*)(Ob + (size_t)(warp * 16 + gid + 8) * DIM + j * 8 + tig * 2) = v1;
    }
}

// ============================================================================
extern "C" void kernel_launch(void* const* d_in, const int* in_sizes, int n_in,
                              void* d_out, int out_size) {
    const float* x  = (const float*)d_in[0];
    const float* Wq = (const float*)d_in[1];
    const float* Wk = (const float*)d_in[2];
    const float* Wv = (const float*)d_in[3];
    const float* Wo = (const float*)d_in[4];
    const float* bo = (const float*)d_in[5];
    float* out = (float*)d_out;

    float *q, *k, *v, *ao;
    cudaGetSymbolAddress((void**)&q, g_q);
    cudaGetSymbolAddress((void**)&k, g_k);
    cudaGetSymbolAddress((void**)&v, g_v);
    cudaGetSymbolAddress((void**)&ao, g_ao);

    const int gsm = 18432 * 4;   // 73728 B
    static bool attr_done = false;
    if (!attr_done) {
        cudaFuncSetAttribute(gemm_qkv, cudaFuncAttributeMaxDynamicSharedMemorySize, gsm);
        cudaFuncSetAttribute(gemm_out, cudaFuncAttributeMaxDynamicSharedMemorySize, gsm);
        int asm_sz = (64 * 68 + 64 * 72 + 128 * 68) * 4;
        cudaFuncSetAttribute(attn_kernel, cudaFuncAttributeMaxDynamicSharedMemorySize, asm_sz);
        attr_done = true;
    }

    gemm_qkv<<<dim3(DIM / 128, ROWS / 128, 3), 256, gsm>>>(x, Wq, Wk, Wv, q, k, v);

    int npairs = ROWS * (DIM / 2);
    rope_kernel<<<(npairs + 255) / 256, 256>>>(q);
    rope_kernel<<<(npairs + 255) / 256, 256>>>(k);

    int asm_sz = (64 * 68 + 64 * 72 + 128 * 68) * 4;   // 70656 B
    attn_kernel<<<dim3(SEQ / 128, BATCH * NH), 256, asm_sz>>>(q, k, v, ao);

    gemm_out<<<dim3(DIM / 128, ROWS / 128), 256, gsm>>>(ao, Wo, out, bo);
}